// round 1
// baseline (speedup 1.0000x reference)
#include <cuda_runtime.h>

#define NTOK 4096
#define DDIM 1024
#define EEXP 8
#define FDIM 4096

// ---------------- scratch (device globals: no runtime allocation) ----------
__device__ int    d_routes[NTOK];
__device__ float  d_scale[NTOK];
__device__ int    d_bucket[EEXP * NTOK];
__device__ int    d_expCount[EEXP];
__device__ float  d_psPartial[512 * EEXP];
__device__ float  d_h[(size_t)NTOK * FDIM];   // 64 MB fp32 hidden activations

// ---------------- init ------------------------------------------------------
__global__ void init_kernel() {
    if (threadIdx.x < EEXP) d_expCount[threadIdx.x] = 0;
}

// ---------------- routing: 1 warp per token ---------------------------------
// fp64 accumulation so our argmax matches the fp32 reference with overwhelming
// probability (an argmax flip on a single token would blow past rel_err 1e-3).
__global__ void route_kernel(const float* __restrict__ x,
                             const float* __restrict__ wsw,
                             const float* __restrict__ bsw) {
    int warp = threadIdx.x >> 5;
    int lane = threadIdx.x & 31;
    int token = blockIdx.x * 8 + warp;

    const float* xr = x + (size_t)token * DDIM;
    double acc[8];
#pragma unroll
    for (int e = 0; e < 8; e++) acc[e] = 0.0;

    for (int i = lane; i < DDIM; i += 32) {
        float xv = xr[i];
        float4 wa = *(const float4*)(wsw + (size_t)i * 8);
        float4 wb = *(const float4*)(wsw + (size_t)i * 8 + 4);
        acc[0] += (double)xv * wa.x;
        acc[1] += (double)xv * wa.y;
        acc[2] += (double)xv * wa.z;
        acc[3] += (double)xv * wa.w;
        acc[4] += (double)xv * wb.x;
        acc[5] += (double)xv * wb.y;
        acc[6] += (double)xv * wb.z;
        acc[7] += (double)xv * wb.w;
    }
#pragma unroll
    for (int e = 0; e < 8; e++) {
#pragma unroll
        for (int off = 16; off > 0; off >>= 1)
            acc[e] += __shfl_down_sync(0xffffffffu, acc[e], off);
    }

    __shared__ float probs[8][8];   // [warp][expert]
    if (lane == 0) {
        float l[8];
#pragma unroll
        for (int e = 0; e < 8; e++) l[e] = (float)acc[e] + bsw[e];
        int am = 0;
        float mx = l[0];
#pragma unroll
        for (int e = 1; e < 8; e++)
            if (l[e] > mx) { mx = l[e]; am = e; }   // first-max like jnp.argmax
        float p[8], sum = 0.0f;
#pragma unroll
        for (int e = 0; e < 8; e++) { p[e] = expf(l[e] - mx); sum += p[e]; }
        float inv = 1.0f / sum;
#pragma unroll
        for (int e = 0; e < 8; e++) probs[warp][e] = p[e] * inv;

        d_routes[token] = am;
        d_scale[token]  = inv;               // p[am] = exp(0) = 1 exactly
        int pos = atomicAdd(&d_expCount[am], 1);
        d_bucket[am * NTOK + pos] = token;
    }
    __syncthreads();
    if (threadIdx.x < 8) {                   // deterministic fixed-order reduce
        float s = 0.0f;
#pragma unroll
        for (int w = 0; w < 8; w++) s += probs[w][threadIdx.x];
        d_psPartial[blockIdx.x * 8 + threadIdx.x] = s;
    }
}

// ---------------- grouped GEMM1: h = relu(scale * x@w1[e] + b1[e]) ----------
// 128x128x8 tile, 256 threads, 8x8 per-thread microtile (4+4 split vectors).
__global__ __launch_bounds__(256, 2)
void gemm1_kernel(const float* __restrict__ x,
                  const float* __restrict__ w1,
                  const float* __restrict__ b1) {
    int e = blockIdx.z;
    int cnt = d_expCount[e];
    int mBase = blockIdx.y * 128;
    if (mBase >= cnt) return;
    int nBase = blockIdx.x * 128;

    const float* Bw = w1 + (size_t)e * DDIM * FDIM;

    __shared__ float As[8][132];   // stride 132: 16B-aligned + conflict-free
    __shared__ float Bs[8][128];

    int tid = threadIdx.x;
    int aRow = tid >> 1, aCol = (tid & 1) * 4;
    int bRow = tid >> 5, bCol = (tid & 31) * 4;

    const float* aPtr = nullptr;
    if (mBase + aRow < cnt)
        aPtr = x + (size_t)d_bucket[e * NTOK + mBase + aRow] * DDIM + aCol;
    const float* bPtr = Bw + (size_t)bRow * FDIM + nBase + bCol;

    int tx = tid & 15, ty = tid >> 4;

    float acc[8][8];
#pragma unroll
    for (int i = 0; i < 8; i++)
#pragma unroll
        for (int j = 0; j < 8; j++) acc[i][j] = 0.0f;

    for (int k0 = 0; k0 < DDIM; k0 += 8) {
        float4 av = aPtr ? *(const float4*)(aPtr + k0)
                         : make_float4(0.f, 0.f, 0.f, 0.f);
        float4 bv = *(const float4*)(bPtr + (size_t)k0 * FDIM);
        As[aCol + 0][aRow] = av.x;
        As[aCol + 1][aRow] = av.y;
        As[aCol + 2][aRow] = av.z;
        As[aCol + 3][aRow] = av.w;
        *(float4*)&Bs[bRow][bCol] = bv;
        __syncthreads();
#pragma unroll
        for (int kk = 0; kk < 8; kk++) {
            float4 a0 = *(const float4*)&As[kk][ty * 4];
            float4 a1 = *(const float4*)&As[kk][64 + ty * 4];
            float4 c0 = *(const float4*)&Bs[kk][tx * 4];
            float4 c1 = *(const float4*)&Bs[kk][64 + tx * 4];
            float ar[8] = {a0.x, a0.y, a0.z, a0.w, a1.x, a1.y, a1.z, a1.w};
            float br[8] = {c0.x, c0.y, c0.z, c0.w, c1.x, c1.y, c1.z, c1.w};
#pragma unroll
            for (int i = 0; i < 8; i++)
#pragma unroll
                for (int j = 0; j < 8; j++)
                    acc[i][j] += ar[i] * br[j];
        }
        __syncthreads();
    }

    float4 g0 = *(const float4*)(b1 + (size_t)e * FDIM + nBase + tx * 4);
    float4 g1 = *(const float4*)(b1 + (size_t)e * FDIM + nBase + 64 + tx * 4);
    float bb[8] = {g0.x, g0.y, g0.z, g0.w, g1.x, g1.y, g1.z, g1.w};

#pragma unroll
    for (int i = 0; i < 8; i++) {
        int mLoc = (i < 4) ? (ty * 4 + i) : (64 + ty * 4 + i - 4);
        int m = mBase + mLoc;
        if (m >= cnt) continue;
        int token = d_bucket[e * NTOK + m];
        float s = d_scale[token];
        float* hr = d_h + (size_t)token * FDIM + nBase;
        float4 o0, o1;
        o0.x = fmaxf(acc[i][0] * s + bb[0], 0.f);
        o0.y = fmaxf(acc[i][1] * s + bb[1], 0.f);
        o0.z = fmaxf(acc[i][2] * s + bb[2], 0.f);
        o0.w = fmaxf(acc[i][3] * s + bb[3], 0.f);
        o1.x = fmaxf(acc[i][4] * s + bb[4], 0.f);
        o1.y = fmaxf(acc[i][5] * s + bb[5], 0.f);
        o1.z = fmaxf(acc[i][6] * s + bb[6], 0.f);
        o1.w = fmaxf(acc[i][7] * s + bb[7], 0.f);
        *(float4*)(hr + tx * 4) = o0;
        *(float4*)(hr + 64 + tx * 4) = o1;
    }
}

// ---------------- grouped GEMM2: out[token] = h@w2[e] + b2[e] ---------------
__global__ __launch_bounds__(256, 2)
void gemm2_kernel(const float* __restrict__ w2,
                  const float* __restrict__ b2,
                  float* __restrict__ out) {
    int e = blockIdx.z;
    int cnt = d_expCount[e];
    int mBase = blockIdx.y * 128;
    if (mBase >= cnt) return;
    int nBase = blockIdx.x * 128;

    const float* Bw = w2 + (size_t)e * FDIM * DDIM;

    __shared__ float As[8][132];
    __shared__ float Bs[8][128];

    int tid = threadIdx.x;
    int aRow = tid >> 1, aCol = (tid & 1) * 4;
    int bRow = tid >> 5, bCol = (tid & 31) * 4;

    const float* aPtr = nullptr;
    if (mBase + aRow < cnt)
        aPtr = d_h + (size_t)d_bucket[e * NTOK + mBase + aRow] * FDIM + aCol;
    const float* bPtr = Bw + (size_t)bRow * DDIM + nBase + bCol;

    int tx = tid & 15, ty = tid >> 4;

    float acc[8][8];
#pragma unroll
    for (int i = 0; i < 8; i++)
#pragma unroll
        for (int j = 0; j < 8; j++) acc[i][j] = 0.0f;

    for (int k0 = 0; k0 < FDIM; k0 += 8) {
        float4 av = aPtr ? *(const float4*)(aPtr + k0)
                         : make_float4(0.f, 0.f, 0.f, 0.f);
        float4 bv = *(const float4*)(bPtr + (size_t)k0 * DDIM);
        As[aCol + 0][aRow] = av.x;
        As[aCol + 1][aRow] = av.y;
        As[aCol + 2][aRow] = av.z;
        As[aCol + 3][aRow] = av.w;
        *(float4*)&Bs[bRow][bCol] = bv;
        __syncthreads();
#pragma unroll
        for (int kk = 0; kk < 8; kk++) {
            float4 a0 = *(const float4*)&As[kk][ty * 4];
            float4 a1 = *(const float4*)&As[kk][64 + ty * 4];
            float4 c0 = *(const float4*)&Bs[kk][tx * 4];
            float4 c1 = *(const float4*)&Bs[kk][64 + tx * 4];
            float ar[8] = {a0.x, a0.y, a0.z, a0.w, a1.x, a1.y, a1.z, a1.w};
            float br[8] = {c0.x, c0.y, c0.z, c0.w, c1.x, c1.y, c1.z, c1.w};
#pragma unroll
            for (int i = 0; i < 8; i++)
#pragma unroll
                for (int j = 0; j < 8; j++)
                    acc[i][j] += ar[i] * br[j];
        }
        __syncthreads();
    }

    float4 g0 = *(const float4*)(b2 + (size_t)e * DDIM + nBase + tx * 4);
    float4 g1 = *(const float4*)(b2 + (size_t)e * DDIM + nBase + 64 + tx * 4);
    float bb[8] = {g0.x, g0.y, g0.z, g0.w, g1.x, g1.y, g1.z, g1.w};

#pragma unroll
    for (int i = 0; i < 8; i++) {
        int mLoc = (i < 4) ? (ty * 4 + i) : (64 + ty * 4 + i - 4);
        int m = mBase + mLoc;
        if (m >= cnt) continue;
        int token = d_bucket[e * NTOK + m];
        float* orow = out + (size_t)token * DDIM + nBase;
        float4 o0, o1;
        o0.x = acc[i][0] + bb[0];
        o0.y = acc[i][1] + bb[1];
        o0.z = acc[i][2] + bb[2];
        o0.w = acc[i][3] + bb[3];
        o1.x = acc[i][4] + bb[4];
        o1.y = acc[i][5] + bb[5];
        o1.z = acc[i][6] + bb[6];
        o1.w = acc[i][7] + bb[7];
        *(float4*)(orow + tx * 4) = o0;
        *(float4*)(orow + 64 + tx * 4) = o1;
    }
}

// ---------------- finalize: counts, route_prob.sum(0), n_dropped ------------
__global__ void finalize_kernel(float* __restrict__ out, int out_size) {
    int e = threadIdx.x;
    if (e >= 8) return;
    float s = 0.0f;
    for (int b = 0; b < 512; b++) s += d_psPartial[b * 8 + e];
    const int base = NTOK * DDIM;               // 4194304
    if (base + e < out_size)      out[base + e]     = (float)d_expCount[e];
    if (base + 8 + e < out_size)  out[base + 8 + e] = s;
    if (e == 0 && base + 16 < out_size) out[base + 16] = 0.0f;  // n_dropped=0
}

// ---------------- launch -----------------------------------------------------
extern "C" void kernel_launch(void* const* d_in, const int* in_sizes, int n_in,
                              void* d_out, int out_size) {
    const float* x   = (const float*)d_in[0];
    const float* wsw = (const float*)d_in[1];
    const float* bsw = (const float*)d_in[2];
    const float* w1  = (const float*)d_in[3];
    const float* b1  = (const float*)d_in[4];
    const float* w2  = (const float*)d_in[5];
    const float* b2  = (const float*)d_in[6];
    float* out = (float*)d_out;

    init_kernel<<<1, 32>>>();
    route_kernel<<<512, 256>>>(x, wsw, bsw);
    gemm1_kernel<<<dim3(FDIM / 128, NTOK / 128, EEXP), 256>>>(x, w1, b1);
    gemm2_kernel<<<dim3(DDIM / 128, NTOK / 128, EEXP), 256>>>(w2, b2, out);
    finalize_kernel<<<1, 8>>>(out, out_size);
}

// round 3
// speedup vs baseline: 1.5969x; 1.5969x over previous
#include <cuda_runtime.h>
#include <cuda_bf16.h>
#include <cstdint>

#define NTOK 4096
#define DDIM 1024
#define EEXP 8
#define FDIM 4096

#define BM 128
#define BN 128
#define BK 32

// smem stage layout: A_hi, A_lo, B_hi, B_lo each 128 rows x 80 bytes
#define ROWB     80
#define OBJ      (128 * ROWB)          // 10240
#define OFF_AH   0
#define OFF_AL   (OBJ)
#define OFF_BH   (2 * OBJ)
#define OFF_BL   (3 * OBJ)
#define STAGE    (4 * OBJ)             // 40960
#define SMEM_TOTAL (2 * STAGE)         // 81920

// ---------------- scratch ---------------------------------------------------
__device__ int    d_bucket[EEXP * NTOK];
__device__ int    d_expCount[EEXP];
__device__ float  d_scale[NTOK];
__device__ float  d_psPartial[512 * EEXP];
__device__ __nv_bfloat16 d_x_hi[(size_t)NTOK * DDIM];
__device__ __nv_bfloat16 d_x_lo[(size_t)NTOK * DDIM];
__device__ __nv_bfloat16 d_w1t_hi[(size_t)EEXP * FDIM * DDIM]; // [E][F][D]
__device__ __nv_bfloat16 d_w1t_lo[(size_t)EEXP * FDIM * DDIM];
__device__ __nv_bfloat16 d_w2t_hi[(size_t)EEXP * DDIM * FDIM]; // [E][D][F]
__device__ __nv_bfloat16 d_w2t_lo[(size_t)EEXP * DDIM * FDIM];
__device__ __nv_bfloat16 d_h_hi[(size_t)NTOK * FDIM];
__device__ __nv_bfloat16 d_h_lo[(size_t)NTOK * FDIM];

// ---------------- helpers ---------------------------------------------------
__device__ __forceinline__ uint32_t smem_u32(const void* p) {
    uint32_t a;
    asm("{ .reg .u64 t; cvta.to.shared.u64 t, %1; cvt.u32.u64 %0, t; }"
        : "=r"(a) : "l"(p));
    return a;
}

__device__ __forceinline__ void cp16(uint32_t saddr, const void* gaddr) {
    asm volatile("cp.async.cg.shared.global [%0], [%1], 16;"
                 :: "r"(saddr), "l"(gaddr));
}
__device__ __forceinline__ void cp_commit() {
    asm volatile("cp.async.commit_group;" ::: "memory");
}
__device__ __forceinline__ void cp_wait0() {
    asm volatile("cp.async.wait_group %0;" :: "n"(0) : "memory");
}

__device__ __forceinline__ void ldm4(uint32_t* r, uint32_t a) {
    asm volatile("ldmatrix.sync.aligned.m8n8.x4.shared.b16 {%0,%1,%2,%3}, [%4];"
                 : "=r"(r[0]), "=r"(r[1]), "=r"(r[2]), "=r"(r[3]) : "r"(a));
}

__device__ __forceinline__ void mma16816(float* c, const uint32_t* a, const uint32_t* b) {
    asm volatile("mma.sync.aligned.m16n8k16.row.col.f32.bf16.bf16.f32 "
                 "{%0,%1,%2,%3}, {%4,%5,%6,%7}, {%8,%9}, {%0,%1,%2,%3};"
                 : "+f"(c[0]), "+f"(c[1]), "+f"(c[2]), "+f"(c[3])
                 : "r"(a[0]), "r"(a[1]), "r"(a[2]), "r"(a[3]),
                   "r"(b[0]), "r"(b[1]));
}

__device__ __forceinline__ void split2(float v0, float v1, uint32_t& hw, uint32_t& lw) {
    __nv_bfloat162 H;
    H.x = __float2bfloat16(v0);
    H.y = __float2bfloat16(v1);
    float l0 = v0 - __bfloat162float(H.x);
    float l1 = v1 - __bfloat162float(H.y);
    __nv_bfloat162 L;
    L.x = __float2bfloat16(l0);
    L.y = __float2bfloat16(l1);
    hw = *reinterpret_cast<uint32_t*>(&H);
    lw = *reinterpret_cast<uint32_t*>(&L);
}

// ---------------- init ------------------------------------------------------
__global__ void init_kernel() {
    if (threadIdx.x < EEXP) d_expCount[threadIdx.x] = 0;
}

// ---------------- routing (1 warp / token, fp64 accumulation) ---------------
__global__ void route_kernel(const float* __restrict__ x,
                             const float* __restrict__ wsw,
                             const float* __restrict__ bsw) {
    int warp = threadIdx.x >> 5;
    int lane = threadIdx.x & 31;
    int token = blockIdx.x * 8 + warp;

    const float* xr = x + (size_t)token * DDIM;
    double acc[8];
#pragma unroll
    for (int e = 0; e < 8; e++) acc[e] = 0.0;

    for (int i = lane; i < DDIM; i += 32) {
        float xv = xr[i];
        float4 wa = *(const float4*)(wsw + (size_t)i * 8);
        float4 wb = *(const float4*)(wsw + (size_t)i * 8 + 4);
        acc[0] += (double)xv * wa.x;
        acc[1] += (double)xv * wa.y;
        acc[2] += (double)xv * wa.z;
        acc[3] += (double)xv * wa.w;
        acc[4] += (double)xv * wb.x;
        acc[5] += (double)xv * wb.y;
        acc[6] += (double)xv * wb.z;
        acc[7] += (double)xv * wb.w;
    }
#pragma unroll
    for (int e = 0; e < 8; e++) {
#pragma unroll
        for (int off = 16; off > 0; off >>= 1)
            acc[e] += __shfl_down_sync(0xffffffffu, acc[e], off);
    }

    __shared__ float probs[8][8];
    if (lane == 0) {
        float l[8];
#pragma unroll
        for (int e = 0; e < 8; e++) l[e] = (float)acc[e] + bsw[e];
        int am = 0;
        float mx = l[0];
#pragma unroll
        for (int e = 1; e < 8; e++)
            if (l[e] > mx) { mx = l[e]; am = e; }
        float p[8], sum = 0.0f;
#pragma unroll
        for (int e = 0; e < 8; e++) { p[e] = expf(l[e] - mx); sum += p[e]; }
        float inv = 1.0f / sum;
#pragma unroll
        for (int e = 0; e < 8; e++) probs[warp][e] = p[e] * inv;

        d_scale[token] = inv;
        int pos = atomicAdd(&d_expCount[am], 1);
        d_bucket[am * NTOK + pos] = token;
    }
    __syncthreads();
    if (threadIdx.x < 8) {
        float s = 0.0f;
#pragma unroll
        for (int w = 0; w < 8; w++) s += probs[w][threadIdx.x];
        d_psPartial[blockIdx.x * 8 + threadIdx.x] = s;
    }
}

// ---------------- split x into bf16 hi/lo -----------------------------------
__global__ void splitx_kernel(const float* __restrict__ x,
                              __nv_bfloat16* __restrict__ hi,
                              __nv_bfloat16* __restrict__ lo) {
    int i = blockIdx.x * blockDim.x + threadIdx.x;   // one float4 each
    float4 v = ((const float4*)x)[i];
    uint32_t h0, l0, h1, l1;
    split2(v.x, v.y, h0, l0);
    split2(v.z, v.w, h1, l1);
    ((uint2*)hi)[i] = make_uint2(h0, h1);
    ((uint2*)lo)[i] = make_uint2(l0, l1);
}

// ---------------- transpose + bf16-split weights ----------------------------
// src [E][R][C] fp32 -> hi/lo [E][C][R] bf16
__global__ void transplit_kernel(const float* __restrict__ src,
                                 __nv_bfloat16* __restrict__ hi,
                                 __nv_bfloat16* __restrict__ lo,
                                 int R, int C) {
    __shared__ float t[32][33];
    size_t base = (size_t)blockIdx.z * R * C;
    int r0 = blockIdx.y * 32, c0 = blockIdx.x * 32;
    int tx = threadIdx.x;
#pragma unroll
    for (int i = threadIdx.y; i < 32; i += 8)
        t[i][tx] = src[base + (size_t)(r0 + i) * C + c0 + tx];
    __syncthreads();
#pragma unroll
    for (int i = threadIdx.y; i < 32; i += 8) {
        float v = t[tx][i];  // = src[r0+tx][c0+i]
        size_t o = base + (size_t)(c0 + i) * R + r0 + tx;
        __nv_bfloat16 h = __float2bfloat16(v);
        hi[o] = h;
        lo[o] = __float2bfloat16(v - __bfloat162float(h));
    }
}

// ---------------- grouped GEMM via mma.sync bf16 split-3 --------------------
// MODE 1: h = relu(scale * x @ w1t + b1), store split bf16 hi/lo
// MODE 2: out = h @ w2t + b2, store fp32 scattered by token
template <int MODE>
__global__ __launch_bounds__(256, 1)
void moe_gemm_kernel(const __nv_bfloat16* __restrict__ aHi,
                     const __nv_bfloat16* __restrict__ aLo,
                     const __nv_bfloat16* __restrict__ wHi,
                     const __nv_bfloat16* __restrict__ wLo,
                     const float* __restrict__ bias,
                     float* __restrict__ out,
                     __nv_bfloat16* __restrict__ oHi,
                     __nv_bfloat16* __restrict__ oLo,
                     int Ntot, int Ktot) {
    int e = blockIdx.z;
    int cnt = d_expCount[e];
    int mBase = blockIdx.y * BM;
    if (mBase >= cnt) return;
    int nBase = blockIdx.x * BN;

    extern __shared__ char smem[];
    uint32_t sb = smem_u32(smem);
    int tid = threadIdx.x;
    int wid = tid >> 5;
    int lane = tid & 31;

    // ---- loader assignment: thread -> (row, 32B half) ----
    int r2 = tid >> 1;
    int hb = tid & 1;
    bool aValid = (mBase + r2) < cnt;
    int aTok = aValid ? d_bucket[e * NTOK + mBase + r2] : d_bucket[e * NTOK];
    const __nv_bfloat16* aH = aHi + (size_t)aTok * Ktot + hb * 16;
    const __nv_bfloat16* aL = aLo + (size_t)aTok * Ktot + hb * 16;
    size_t wBase = ((size_t)e * Ntot + nBase) * (size_t)Ktot;
    const __nv_bfloat16* bH = wHi + wBase + (size_t)r2 * Ktot + hb * 16;
    const __nv_bfloat16* bL = wLo + wBase + (size_t)r2 * Ktot + hb * 16;
    uint32_t sRow = sb + r2 * ROWB + hb * 32;

    auto load_stage = [&](int st, int k0) {
        uint32_t s0 = sRow + st * STAGE;
        cp16(s0 + OFF_AH,      aH + k0);
        cp16(s0 + OFF_AH + 16, aH + k0 + 8);
        cp16(s0 + OFF_AL,      aL + k0);
        cp16(s0 + OFF_AL + 16, aL + k0 + 8);
        cp16(s0 + OFF_BH,      bH + k0);
        cp16(s0 + OFF_BH + 16, bH + k0 + 8);
        cp16(s0 + OFF_BL,      bL + k0);
        cp16(s0 + OFF_BL + 16, bL + k0 + 8);
    };

    // ---- compute assignment ----
    int warpM = wid >> 1;           // 0..3
    int warpN = wid & 1;            // 0..1
    int m0 = warpM * 32;
    int n0 = warpN * 64;

    float acc[16][4];
#pragma unroll
    for (int i = 0; i < 16; i++)
#pragma unroll
        for (int j = 0; j < 4; j++) acc[i][j] = 0.0f;

    // ldmatrix lane addressing
    int aRowL = m0 + (lane & 15);
    int aColB = (lane >> 4) * 16;                       // bytes
    int bRowL = n0 + ((lane >> 4) & 1) * 8 + (lane & 7);
    int bColB = ((lane >> 3) & 1) * 16;                 // bytes

    const int T = Ktot / BK;

    load_stage(0, 0);
    cp_commit();

    for (int t = 0; t < T; t++) {
        int st = t & 1;
        cp_wait0();
        __syncthreads();
        if (t + 1 < T) {
            load_stage(st ^ 1, (t + 1) * BK);
            cp_commit();
        }
        uint32_t base = sb + st * STAGE;
#pragma unroll
        for (int s = 0; s < 2; s++) {     // two k16 steps per stage
            uint32_t aAddr = base + OFF_AH + aRowL * ROWB + aColB + s * 32;
            uint32_t ah0[4], ah1[4], al0[4], al1[4];
            ldm4(ah0, aAddr);
            ldm4(ah1, aAddr + 16 * ROWB);
            ldm4(al0, aAddr + (OFF_AL - OFF_AH));
            ldm4(al1, aAddr + (OFF_AL - OFF_AH) + 16 * ROWB);

            uint32_t bAddr = base + OFF_BH + bRowL * ROWB + bColB + s * 32;
            uint32_t bh[16], bl[16];
#pragma unroll
            for (int j = 0; j < 4; j++) {
                ldm4(&bh[j * 4], bAddr + j * 16 * ROWB);
                ldm4(&bl[j * 4], bAddr + (OFF_BL - OFF_BH) + j * 16 * ROWB);
            }
#pragma unroll
            for (int mi = 0; mi < 2; mi++) {
                const uint32_t* Ah = mi ? ah1 : ah0;
                const uint32_t* Al = mi ? al1 : al0;
#pragma unroll
                for (int nj = 0; nj < 8; nj++) {
                    float* c = acc[mi * 8 + nj];
                    mma16816(c, Ah, &bh[nj * 2]);
                    mma16816(c, Ah, &bl[nj * 2]);
                    mma16816(c, Al, &bh[nj * 2]);
                }
            }
        }
        __syncthreads();
    }

    // ---- epilogue ----
#pragma unroll
    for (int mi = 0; mi < 2; mi++) {
#pragma unroll
        for (int half = 0; half < 2; half++) {
            int r = m0 + mi * 16 + half * 8 + (lane >> 2);
            int m = mBase + r;
            if (m >= cnt) continue;
            int token = d_bucket[e * NTOK + m];
            float sc = (MODE == 1) ? d_scale[token] : 1.0f;
#pragma unroll
            for (int nj = 0; nj < 8; nj++) {
                int col = nBase + n0 + nj * 8 + (lane & 3) * 2;
                float2 bv = *(const float2*)(bias + (size_t)e * Ntot + col);
                float v0 = acc[mi * 8 + nj][half * 2];
                float v1 = acc[mi * 8 + nj][half * 2 + 1];
                if (MODE == 1) {
                    v0 = fmaxf(v0 * sc + bv.x, 0.f);
                    v1 = fmaxf(v1 * sc + bv.y, 0.f);
                    uint32_t hw, lw;
                    split2(v0, v1, hw, lw);
                    *(uint32_t*)(oHi + (size_t)token * Ntot + col) = hw;
                    *(uint32_t*)(oLo + (size_t)token * Ntot + col) = lw;
                } else {
                    float2 o;
                    o.x = v0 + bv.x;
                    o.y = v1 + bv.y;
                    *(float2*)(out + (size_t)token * Ntot + col) = o;
                }
            }
        }
    }
}

// ---------------- finalize ---------------------------------------------------
__global__ void finalize_kernel(float* __restrict__ out, int out_size) {
    int e = threadIdx.x;
    if (e >= 8) return;
    float s = 0.0f;
    for (int b = 0; b < 512; b++) s += d_psPartial[b * 8 + e];
    const int base = NTOK * DDIM;
    if (base + e < out_size)     out[base + e]     = (float)d_expCount[e];
    if (base + 8 + e < out_size) out[base + 8 + e] = s;
    if (e == 0 && base + 16 < out_size) out[base + 16] = 0.0f;
}

// ---------------- launch -----------------------------------------------------
extern "C" void kernel_launch(void* const* d_in, const int* in_sizes, int n_in,
                              void* d_out, int out_size) {
    const float* x   = (const float*)d_in[0];
    const float* wsw = (const float*)d_in[1];
    const float* bsw = (const float*)d_in[2];
    const float* w1  = (const float*)d_in[3];
    const float* b1  = (const float*)d_in[4];
    const float* w2  = (const float*)d_in[5];
    const float* b2  = (const float*)d_in[6];
    float* out = (float*)d_out;

    cudaFuncSetAttribute(moe_gemm_kernel<1>,
                         cudaFuncAttributeMaxDynamicSharedMemorySize, SMEM_TOTAL);
    cudaFuncSetAttribute(moe_gemm_kernel<2>,
                         cudaFuncAttributeMaxDynamicSharedMemorySize, SMEM_TOTAL);

    __nv_bfloat16 *xh, *xl, *w1h, *w1l, *w2h, *w2l, *hh, *hl;
    cudaGetSymbolAddress((void**)&xh, d_x_hi);
    cudaGetSymbolAddress((void**)&xl, d_x_lo);
    cudaGetSymbolAddress((void**)&w1h, d_w1t_hi);
    cudaGetSymbolAddress((void**)&w1l, d_w1t_lo);
    cudaGetSymbolAddress((void**)&w2h, d_w2t_hi);
    cudaGetSymbolAddress((void**)&w2l, d_w2t_lo);
    cudaGetSymbolAddress((void**)&hh, d_h_hi);
    cudaGetSymbolAddress((void**)&hl, d_h_lo);

    init_kernel<<<1, 32>>>();
    route_kernel<<<512, 256>>>(x, wsw, bsw);
    splitx_kernel<<<NTOK * DDIM / 4 / 256, 256>>>(x, xh, xl);
    // w1 [E][D][F] -> w1t [E][F][D]
    transplit_kernel<<<dim3(FDIM / 32, DDIM / 32, EEXP), dim3(32, 8)>>>(w1, w1h, w1l, DDIM, FDIM);
    // w2 [E][F][D] -> w2t [E][D][F]
    transplit_kernel<<<dim3(DDIM / 32, FDIM / 32, EEXP), dim3(32, 8)>>>(w2, w2h, w2l, FDIM, DDIM);

    moe_gemm_kernel<1><<<dim3(FDIM / BN, NTOK / BM, EEXP), 256, SMEM_TOTAL>>>(
        xh, xl, w1h, w1l, b1, nullptr, hh, hl, FDIM, DDIM);
    moe_gemm_kernel<2><<<dim3(DDIM / BN, NTOK / BM, EEXP), 256, SMEM_TOTAL>>>(
        hh, hl, w2h, w2l, b2, out, nullptr, nullptr, DDIM, FDIM);

    finalize_kernel<<<1, 8>>>(out, out_size);
}

// round 4
// speedup vs baseline: 1.9091x; 1.1955x over previous
#include <cuda_runtime.h>
#include <cuda_bf16.h>
#include <cstdint>

#define NTOK 4096
#define DDIM 1024
#define EEXP 8
#define FDIM 4096

#define BM 128
#define BN 128
#define BK 32

// smem stage layout:
//   A_hi/A_lo: 128 rows x 80B (32 bf16 + 16B pad)
//   B_hi/B_lo: 32 rows (k) x 272B (128 bf16 + 16B pad)
#define AROWB   80
#define BROWB   272
#define OFF_AH  0
#define OFF_AL  10240
#define OFF_BH  20480
#define OFF_BL  29184
#define STAGE   37888
#define SMEM_TOTAL (2 * STAGE)   // 75776

// ---------------- scratch ---------------------------------------------------
__device__ int    d_bucket[EEXP * NTOK];
__device__ int    d_expCount[EEXP];
__device__ float  d_scale[NTOK];
__device__ float  d_psPartial[512 * EEXP];
__device__ __nv_bfloat16 d_h_hi[(size_t)NTOK * FDIM];
__device__ __nv_bfloat16 d_h_lo[(size_t)NTOK * FDIM];

// ---------------- helpers ---------------------------------------------------
__device__ __forceinline__ uint32_t smem_u32(const void* p) {
    uint32_t a;
    asm("{ .reg .u64 t; cvta.to.shared.u64 t, %1; cvt.u32.u64 %0, t; }"
        : "=r"(a) : "l"(p));
    return a;
}

__device__ __forceinline__ void ldm4(uint32_t* r, uint32_t a) {
    asm volatile("ldmatrix.sync.aligned.m8n8.x4.shared.b16 {%0,%1,%2,%3}, [%4];"
                 : "=r"(r[0]), "=r"(r[1]), "=r"(r[2]), "=r"(r[3]) : "r"(a));
}
__device__ __forceinline__ void ldm4t(uint32_t* r, uint32_t a) {
    asm volatile("ldmatrix.sync.aligned.m8n8.x4.trans.shared.b16 {%0,%1,%2,%3}, [%4];"
                 : "=r"(r[0]), "=r"(r[1]), "=r"(r[2]), "=r"(r[3]) : "r"(a));
}

__device__ __forceinline__ void mma16816(float* c, const uint32_t* a, const uint32_t* b) {
    asm volatile("mma.sync.aligned.m16n8k16.row.col.f32.bf16.bf16.f32 "
                 "{%0,%1,%2,%3}, {%4,%5,%6,%7}, {%8,%9}, {%0,%1,%2,%3};"
                 : "+f"(c[0]), "+f"(c[1]), "+f"(c[2]), "+f"(c[3])
                 : "r"(a[0]), "r"(a[1]), "r"(a[2]), "r"(a[3]),
                   "r"(b[0]), "r"(b[1]));
}

__device__ __forceinline__ void split2(float v0, float v1, uint32_t& hw, uint32_t& lw) {
    __nv_bfloat162 H;
    H.x = __float2bfloat16(v0);
    H.y = __float2bfloat16(v1);
    float l0 = v0 - __bfloat162float(H.x);
    float l1 = v1 - __bfloat162float(H.y);
    __nv_bfloat162 L;
    L.x = __float2bfloat16(l0);
    L.y = __float2bfloat16(l1);
    hw = *reinterpret_cast<uint32_t*>(&H);
    lw = *reinterpret_cast<uint32_t*>(&L);
}

__device__ __forceinline__ void split_f4x2(const float4& f0, const float4& f1,
                                           uint4& H, uint4& L) {
    split2(f0.x, f0.y, H.x, L.x);
    split2(f0.z, f0.w, H.y, L.y);
    split2(f1.x, f1.y, H.z, L.z);
    split2(f1.z, f1.w, H.w, L.w);
}

// ---------------- init ------------------------------------------------------
__global__ void init_kernel() {
    if (threadIdx.x < EEXP) d_expCount[threadIdx.x] = 0;
}

// ---------------- routing (1 warp / token, fp64 accumulation) ---------------
__global__ void route_kernel(const float* __restrict__ x,
                             const float* __restrict__ wsw,
                             const float* __restrict__ bsw) {
    int warp = threadIdx.x >> 5;
    int lane = threadIdx.x & 31;
    int token = blockIdx.x * 8 + warp;

    const float* xr = x + (size_t)token * DDIM;
    double acc[8];
#pragma unroll
    for (int e = 0; e < 8; e++) acc[e] = 0.0;

    for (int i = lane; i < DDIM; i += 32) {
        float xv = xr[i];
        float4 wa = *(const float4*)(wsw + (size_t)i * 8);
        float4 wb = *(const float4*)(wsw + (size_t)i * 8 + 4);
        acc[0] += (double)xv * wa.x;
        acc[1] += (double)xv * wa.y;
        acc[2] += (double)xv * wa.z;
        acc[3] += (double)xv * wa.w;
        acc[4] += (double)xv * wb.x;
        acc[5] += (double)xv * wb.y;
        acc[6] += (double)xv * wb.z;
        acc[7] += (double)xv * wb.w;
    }
#pragma unroll
    for (int e = 0; e < 8; e++) {
#pragma unroll
        for (int off = 16; off > 0; off >>= 1)
            acc[e] += __shfl_down_sync(0xffffffffu, acc[e], off);
    }

    __shared__ float probs[8][8];
    if (lane == 0) {
        float l[8];
#pragma unroll
        for (int e = 0; e < 8; e++) l[e] = (float)acc[e] + bsw[e];
        int am = 0;
        float mx = l[0];
#pragma unroll
        for (int e = 1; e < 8; e++)
            if (l[e] > mx) { mx = l[e]; am = e; }
        float p[8], sum = 0.0f;
#pragma unroll
        for (int e = 0; e < 8; e++) { p[e] = expf(l[e] - mx); sum += p[e]; }
        float inv = 1.0f / sum;
#pragma unroll
        for (int e = 0; e < 8; e++) probs[warp][e] = p[e] * inv;

        d_scale[token] = inv;
        int pos = atomicAdd(&d_expCount[am], 1);
        d_bucket[am * NTOK + pos] = token;
    }
    __syncthreads();
    if (threadIdx.x < 8) {
        float s = 0.0f;
#pragma unroll
        for (int w = 0; w < 8; w++) s += probs[w][threadIdx.x];
        d_psPartial[blockIdx.x * 8 + threadIdx.x] = s;
    }
}

// ---------------- grouped GEMM, split-bf16 3-pass, in-flight conversion -----
// MODE 1: h = relu(scale * x @ w1 + b1); A = x fp32 (gather+split), W = w1 fp32
// MODE 2: out = h @ w2 + b2;            A = h split bf16,        W = w2 fp32
// W native layout [K][N] (k-major rows); B fragments via ldmatrix.trans.
template <int MODE>
__global__ __launch_bounds__(256, 1)
void moe_gemm_kernel(const float* __restrict__ xA,
                     const __nv_bfloat16* __restrict__ aHi,
                     const __nv_bfloat16* __restrict__ aLo,
                     const float* __restrict__ W,
                     const float* __restrict__ bias,
                     float* __restrict__ out,
                     __nv_bfloat16* __restrict__ oHi,
                     __nv_bfloat16* __restrict__ oLo,
                     int Ntot, int Ktot) {
    int e = blockIdx.z;
    int cnt = d_expCount[e];
    int mBase = blockIdx.y * BM;
    if (mBase >= cnt) return;
    int nBase = blockIdx.x * BN;

    extern __shared__ char smem[];
    uint32_t sb = smem_u32(smem);
    int tid = threadIdx.x;
    int wid = tid >> 5;
    int lane = tid & 31;

    // ---- loader assignment ----
    // A: thread -> (row r2 = tid>>1, k-half hb = tid&1), 16 k-values each
    int r2 = tid >> 1;
    int hb = tid & 1;
    bool aValid = (mBase + r2) < cnt;
    int aTok = aValid ? d_bucket[e * NTOK + mBase + r2] : d_bucket[e * NTOK];
    const float* aPtrF = xA ? (xA + (size_t)aTok * Ktot + hb * 16) : nullptr;
    const uint4* aPtrH = (const uint4*)(aHi + (size_t)aTok * (size_t)Ktot) + hb * 2;
    const uint4* aPtrL = (const uint4*)(aLo + (size_t)aTok * (size_t)Ktot) + hb * 2;
    uint32_t sA = sb + r2 * AROWB + hb * 32;

    // B: thread -> (k-row rowB = tid>>3, 16-col seg = tid&7)
    int rowB = tid >> 3;
    int segB = tid & 7;
    const float* bPtr = W + (size_t)e * (size_t)Ktot * Ntot +
                        (size_t)rowB * Ntot + nBase + segB * 16;
    uint32_t sB = sb + rowB * BROWB + segB * 32;

    // ---- staging registers ----
    float4 rB0, rB1, rB2, rB3;
    float4 rA0, rA1, rA2, rA3;         // MODE 1
    uint4 rAH0, rAH1, rAL0, rAL1;      // MODE 2

    auto ldg_stage = [&](int k0) {
        if (MODE == 1) {
            rA0 = *(const float4*)(aPtrF + k0);
            rA1 = *(const float4*)(aPtrF + k0 + 4);
            rA2 = *(const float4*)(aPtrF + k0 + 8);
            rA3 = *(const float4*)(aPtrF + k0 + 12);
        } else {
            int u = k0 >> 3;
            rAH0 = aPtrH[u];
            rAH1 = aPtrH[u + 1];
            rAL0 = aPtrL[u];
            rAL1 = aPtrL[u + 1];
        }
        const float* bg = bPtr + (size_t)k0 * Ntot;
        rB0 = *(const float4*)(bg);
        rB1 = *(const float4*)(bg + 4);
        rB2 = *(const float4*)(bg + 8);
        rB3 = *(const float4*)(bg + 12);
    };

    auto sts_stage = [&](int st) {
        uint32_t base = st * STAGE;
        if (MODE == 1) {
            uint4 H0, L0, H1, L1;
            split_f4x2(rA0, rA1, H0, L0);
            split_f4x2(rA2, rA3, H1, L1);
            *(uint4*)(smem + base + OFF_AH + (sA - sb))      = H0;
            *(uint4*)(smem + base + OFF_AH + (sA - sb) + 16) = H1;
            *(uint4*)(smem + base + OFF_AL + (sA - sb))      = L0;
            *(uint4*)(smem + base + OFF_AL + (sA - sb) + 16) = L1;
        } else {
            *(uint4*)(smem + base + OFF_AH + (sA - sb))      = rAH0;
            *(uint4*)(smem + base + OFF_AH + (sA - sb) + 16) = rAH1;
            *(uint4*)(smem + base + OFF_AL + (sA - sb))      = rAL0;
            *(uint4*)(smem + base + OFF_AL + (sA - sb) + 16) = rAL1;
        }
        uint4 H0, L0, H1, L1;
        split_f4x2(rB0, rB1, H0, L0);
        split_f4x2(rB2, rB3, H1, L1);
        *(uint4*)(smem + base + OFF_BH + (sB - sb))      = H0;
        *(uint4*)(smem + base + OFF_BH + (sB - sb) + 16) = H1;
        *(uint4*)(smem + base + OFF_BL + (sB - sb))      = L0;
        *(uint4*)(smem + base + OFF_BL + (sB - sb) + 16) = L1;
    };

    // ---- compute assignment: 4 warpM x 2 warpN, warp tile 32x64 ----
    int warpM = wid >> 1;
    int warpN = wid & 1;
    int m0 = warpM * 32;
    int n0 = warpN * 64;

    float acc[16][4];
#pragma unroll
    for (int i = 0; i < 16; i++)
#pragma unroll
        for (int j = 0; j < 4; j++) acc[i][j] = 0.0f;

    // A ldmatrix lane addressing (row-major m16k16 fragments)
    int aRowL = m0 + (lane & 15);
    int aColB = (lane >> 4) * 16;
    // B ldmatrix.trans lane addressing: smem is [k][n]; trans yields col-major frags
    int bKoff = (lane & 7) + ((lane >> 3) & 1) * 8;   // k row within k16
    int bNoff = ((lane >> 4) & 1) * 8;                // n sub-block

    const int T = Ktot / BK;

    ldg_stage(0);
    sts_stage(0);
    __syncthreads();

    for (int t = 0; t < T; t++) {
        int st = t & 1;
        if (t + 1 < T) ldg_stage((t + 1) * BK);

        uint32_t base = sb + st * STAGE;
#pragma unroll
        for (int s = 0; s < 2; s++) {
            uint32_t aAddr = base + OFF_AH + aRowL * AROWB + aColB + s * 32;
            uint32_t ah0[4], ah1[4], al0[4], al1[4];
            ldm4(ah0, aAddr);
            ldm4(ah1, aAddr + 16 * AROWB);
            ldm4(al0, aAddr + (OFF_AL - OFF_AH));
            ldm4(al1, aAddr + (OFF_AL - OFF_AH) + 16 * AROWB);

            uint32_t bh[16], bl[16];
#pragma unroll
            for (int l = 0; l < 4; l++) {
                uint32_t bAddr = base + OFF_BH + (s * 16 + bKoff) * BROWB +
                                 (n0 + l * 16 + bNoff) * 2;
                ldm4t(&bh[l * 4], bAddr);
                ldm4t(&bl[l * 4], bAddr + (OFF_BL - OFF_BH));
            }
            // pass-major ordering: 16 independent MMAs per pass
#pragma unroll
            for (int mi = 0; mi < 2; mi++)
#pragma unroll
                for (int nj = 0; nj < 8; nj++)
                    mma16816(acc[mi * 8 + nj], mi ? ah1 : ah0, &bh[nj * 2]);
#pragma unroll
            for (int mi = 0; mi < 2; mi++)
#pragma unroll
                for (int nj = 0; nj < 8; nj++)
                    mma16816(acc[mi * 8 + nj], mi ? ah1 : ah0, &bl[nj * 2]);
#pragma unroll
            for (int mi = 0; mi < 2; mi++)
#pragma unroll
                for (int nj = 0; nj < 8; nj++)
                    mma16816(acc[mi * 8 + nj], mi ? al1 : al0, &bh[nj * 2]);
        }
        if (t + 1 < T) sts_stage(st ^ 1);
        __syncthreads();
    }

    // ---- epilogue ----
#pragma unroll
    for (int mi = 0; mi < 2; mi++) {
#pragma unroll
        for (int half = 0; half < 2; half++) {
            int r = m0 + mi * 16 + half * 8 + (lane >> 2);
            int m = mBase + r;
            if (m >= cnt) continue;
            int token = d_bucket[e * NTOK + m];
            float sc = (MODE == 1) ? d_scale[token] : 1.0f;
#pragma unroll
            for (int nj = 0; nj < 8; nj++) {
                int col = nBase + n0 + nj * 8 + (lane & 3) * 2;
                float2 bv = *(const float2*)(bias + (size_t)e * Ntot + col);
                float v0 = acc[mi * 8 + nj][half * 2];
                float v1 = acc[mi * 8 + nj][half * 2 + 1];
                if (MODE == 1) {
                    v0 = fmaxf(v0 * sc + bv.x, 0.f);
                    v1 = fmaxf(v1 * sc + bv.y, 0.f);
                    uint32_t hw, lw;
                    split2(v0, v1, hw, lw);
                    *(uint32_t*)(oHi + (size_t)token * Ntot + col) = hw;
                    *(uint32_t*)(oLo + (size_t)token * Ntot + col) = lw;
                } else {
                    float2 o;
                    o.x = v0 + bv.x;
                    o.y = v1 + bv.y;
                    *(float2*)(out + (size_t)token * Ntot + col) = o;
                }
            }
        }
    }
}

// ---------------- finalize ---------------------------------------------------
__global__ void finalize_kernel(float* __restrict__ out, int out_size) {
    int e = threadIdx.x;
    if (e >= 8) return;
    float s = 0.0f;
    for (int b = 0; b < 512; b++) s += d_psPartial[b * 8 + e];
    const int base = NTOK * DDIM;
    if (base + e < out_size)     out[base + e]     = (float)d_expCount[e];
    if (base + 8 + e < out_size) out[base + 8 + e] = s;
    if (e == 0 && base + 16 < out_size) out[base + 16] = 0.0f;
}

// ---------------- launch -----------------------------------------------------
extern "C" void kernel_launch(void* const* d_in, const int* in_sizes, int n_in,
                              void* d_out, int out_size) {
    const float* x   = (const float*)d_in[0];
    const float* wsw = (const float*)d_in[1];
    const float* bsw = (const float*)d_in[2];
    const float* w1  = (const float*)d_in[3];
    const float* b1  = (const float*)d_in[4];
    const float* w2  = (const float*)d_in[5];
    const float* b2  = (const float*)d_in[6];
    float* out = (float*)d_out;

    cudaFuncSetAttribute(moe_gemm_kernel<1>,
                         cudaFuncAttributeMaxDynamicSharedMemorySize, SMEM_TOTAL);
    cudaFuncSetAttribute(moe_gemm_kernel<2>,
                         cudaFuncAttributeMaxDynamicSharedMemorySize, SMEM_TOTAL);

    __nv_bfloat16 *hh, *hl;
    cudaGetSymbolAddress((void**)&hh, d_h_hi);
    cudaGetSymbolAddress((void**)&hl, d_h_lo);

    init_kernel<<<1, 32>>>();
    route_kernel<<<512, 256>>>(x, wsw, bsw);

    moe_gemm_kernel<1><<<dim3(FDIM / BN, NTOK / BM, EEXP), 256, SMEM_TOTAL>>>(
        x, hh, hl, w1, b1, nullptr, hh, hl, FDIM, DDIM);
    moe_gemm_kernel<2><<<dim3(DDIM / BN, NTOK / BM, EEXP), 256, SMEM_TOTAL>>>(
        nullptr, hh, hl, w2, b2, out, nullptr, nullptr, DDIM, FDIM);

    finalize_kernel<<<1, 8>>>(out, out_size);
}

// round 5
// speedup vs baseline: 2.0314x; 1.0640x over previous
#include <cuda_runtime.h>
#include <cuda_bf16.h>
#include <cstdint>

#define NTOK 4096
#define DDIM 1024
#define EEXP 8
#define FDIM 4096

#define BM 128
#define BN 256
#define BK 32
#define NSTAGE 3

// smem per stage: A hi/lo 128 rows x 80B; B hi/lo 32 rows x 528B
#define AROWB 80
#define BROWB 528
#define OFF_AH 0
#define OFF_AL 10240
#define OFF_BH 20480
#define OFF_BL 37376
#define STAGE  54272
#define SMEM_TOTAL (NSTAGE * STAGE)   // 162816

// ---------------- scratch ---------------------------------------------------
__device__ int    d_bucket[EEXP * NTOK];
__device__ int    d_expCount[EEXP];
__device__ float  d_scale[NTOK];
__device__ float  d_psPartial[512 * EEXP];
__device__ __nv_bfloat16 d_x_hi[(size_t)NTOK * DDIM];
__device__ __nv_bfloat16 d_x_lo[(size_t)NTOK * DDIM];
__device__ __nv_bfloat16 d_w1_hi[(size_t)EEXP * DDIM * FDIM];  // [E][K][N]
__device__ __nv_bfloat16 d_w1_lo[(size_t)EEXP * DDIM * FDIM];
__device__ __nv_bfloat16 d_w2_hi[(size_t)EEXP * FDIM * DDIM];  // [E][K][N]
__device__ __nv_bfloat16 d_w2_lo[(size_t)EEXP * FDIM * DDIM];
__device__ __nv_bfloat16 d_h_hi[(size_t)NTOK * FDIM];
__device__ __nv_bfloat16 d_h_lo[(size_t)NTOK * FDIM];

// ---------------- helpers ---------------------------------------------------
__device__ __forceinline__ uint32_t smem_u32(const void* p) {
    uint32_t a;
    asm("{ .reg .u64 t; cvta.to.shared.u64 t, %1; cvt.u32.u64 %0, t; }"
        : "=r"(a) : "l"(p));
    return a;
}
__device__ __forceinline__ void cp16(uint32_t s, const void* g) {
    asm volatile("cp.async.cg.shared.global [%0], [%1], 16;" :: "r"(s), "l"(g));
}
__device__ __forceinline__ void cp_commit() {
    asm volatile("cp.async.commit_group;" ::: "memory");
}
__device__ __forceinline__ void cp_wait1() {
    asm volatile("cp.async.wait_group 1;" ::: "memory");
}
__device__ __forceinline__ void cp_wait0() {
    asm volatile("cp.async.wait_group 0;" ::: "memory");
}
__device__ __forceinline__ void ldm4(uint32_t* r, uint32_t a) {
    asm volatile("ldmatrix.sync.aligned.m8n8.x4.shared.b16 {%0,%1,%2,%3}, [%4];"
                 : "=r"(r[0]), "=r"(r[1]), "=r"(r[2]), "=r"(r[3]) : "r"(a));
}
__device__ __forceinline__ void ldm4t(uint32_t* r, uint32_t a) {
    asm volatile("ldmatrix.sync.aligned.m8n8.x4.trans.shared.b16 {%0,%1,%2,%3}, [%4];"
                 : "=r"(r[0]), "=r"(r[1]), "=r"(r[2]), "=r"(r[3]) : "r"(a));
}
__device__ __forceinline__ void mma16816(float* c, const uint32_t* a, const uint32_t* b) {
    asm volatile("mma.sync.aligned.m16n8k16.row.col.f32.bf16.bf16.f32 "
                 "{%0,%1,%2,%3}, {%4,%5,%6,%7}, {%8,%9}, {%0,%1,%2,%3};"
                 : "+f"(c[0]), "+f"(c[1]), "+f"(c[2]), "+f"(c[3])
                 : "r"(a[0]), "r"(a[1]), "r"(a[2]), "r"(a[3]),
                   "r"(b[0]), "r"(b[1]));
}
__device__ __forceinline__ void split2(float v0, float v1, uint32_t& hw, uint32_t& lw) {
    __nv_bfloat162 H;
    H.x = __float2bfloat16(v0);
    H.y = __float2bfloat16(v1);
    float l0 = v0 - __bfloat162float(H.x);
    float l1 = v1 - __bfloat162float(H.y);
    __nv_bfloat162 L;
    L.x = __float2bfloat16(l0);
    L.y = __float2bfloat16(l1);
    hw = *reinterpret_cast<uint32_t*>(&H);
    lw = *reinterpret_cast<uint32_t*>(&L);
}

// ---------------- init ------------------------------------------------------
__global__ void init_kernel() {
    if (threadIdx.x < EEXP) d_expCount[threadIdx.x] = 0;
}

// ---------------- routing (1 warp / token, fp64 accumulation) ---------------
__global__ void route_kernel(const float* __restrict__ x,
                             const float* __restrict__ wsw,
                             const float* __restrict__ bsw) {
    int warp = threadIdx.x >> 5;
    int lane = threadIdx.x & 31;
    int token = blockIdx.x * 8 + warp;

    const float* xr = x + (size_t)token * DDIM;
    double acc[8];
#pragma unroll
    for (int e = 0; e < 8; e++) acc[e] = 0.0;

    for (int i = lane; i < DDIM; i += 32) {
        float xv = xr[i];
        float4 wa = *(const float4*)(wsw + (size_t)i * 8);
        float4 wb = *(const float4*)(wsw + (size_t)i * 8 + 4);
        acc[0] += (double)xv * wa.x;
        acc[1] += (double)xv * wa.y;
        acc[2] += (double)xv * wa.z;
        acc[3] += (double)xv * wa.w;
        acc[4] += (double)xv * wb.x;
        acc[5] += (double)xv * wb.y;
        acc[6] += (double)xv * wb.z;
        acc[7] += (double)xv * wb.w;
    }
#pragma unroll
    for (int e = 0; e < 8; e++) {
#pragma unroll
        for (int off = 16; off > 0; off >>= 1)
            acc[e] += __shfl_down_sync(0xffffffffu, acc[e], off);
    }

    __shared__ float probs[8][8];
    if (lane == 0) {
        float l[8];
#pragma unroll
        for (int e = 0; e < 8; e++) l[e] = (float)acc[e] + bsw[e];
        int am = 0;
        float mx = l[0];
#pragma unroll
        for (int e = 1; e < 8; e++)
            if (l[e] > mx) { mx = l[e]; am = e; }
        float p[8], sum = 0.0f;
#pragma unroll
        for (int e = 0; e < 8; e++) { p[e] = expf(l[e] - mx); sum += p[e]; }
        float inv = 1.0f / sum;
#pragma unroll
        for (int e = 0; e < 8; e++) probs[warp][e] = p[e] * inv;

        d_scale[token] = inv;
        int pos = atomicAdd(&d_expCount[am], 1);
        d_bucket[am * NTOK + pos] = token;
    }
    __syncthreads();
    if (threadIdx.x < 8) {
        float s = 0.0f;
#pragma unroll
        for (int w = 0; w < 8; w++) s += probs[w][threadIdx.x];
        d_psPartial[blockIdx.x * 8 + threadIdx.x] = s;
    }
}

// ---------------- elementwise fp32 -> bf16 hi/lo split ----------------------
__global__ void splitf_kernel(const float* __restrict__ src,
                              __nv_bfloat16* __restrict__ hi,
                              __nv_bfloat16* __restrict__ lo) {
    int i = blockIdx.x * blockDim.x + threadIdx.x;   // one float4 each
    float4 v = ((const float4*)src)[i];
    uint32_t h0, l0, h1, l1;
    split2(v.x, v.y, h0, l0);
    split2(v.z, v.w, h1, l1);
    ((uint2*)hi)[i] = make_uint2(h0, h1);
    ((uint2*)lo)[i] = make_uint2(l0, l1);
}

// ---------------- grouped GEMM, all-bf16 cp.async, 3-stage pipeline ---------
// C = A @ W  with split-bf16 3-pass accumulation.
// MODE 1: epilogue relu(scale*acc + b1) -> split store to h hi/lo
// MODE 2: epilogue acc + b2 -> fp32 scatter to out
template <int MODE>
__global__ __launch_bounds__(256, 1)
void moe_gemm_kernel(const __nv_bfloat16* __restrict__ aHi,
                     const __nv_bfloat16* __restrict__ aLo,
                     const __nv_bfloat16* __restrict__ wHi,
                     const __nv_bfloat16* __restrict__ wLo,
                     const float* __restrict__ bias,
                     float* __restrict__ out,
                     __nv_bfloat16* __restrict__ oHi,
                     __nv_bfloat16* __restrict__ oLo,
                     int Ntot, int Ktot) {
    int e = blockIdx.z;
    int cnt = d_expCount[e];
    int mBase = blockIdx.y * BM;
    if (mBase >= cnt) return;
    int nBase = blockIdx.x * BN;

    extern __shared__ char smem[];
    uint32_t sb = smem_u32(smem);
    int tid = threadIdx.x;
    int wid = tid >> 5;
    int lane = tid & 31;

    // ---- loader assignment ----
    int r2 = tid >> 1;              // A row 0..127
    int hb = tid & 1;               // A k-half (16 bf16 = 32B)
    bool aValid = (mBase + r2) < cnt;
    int aTok = aValid ? d_bucket[e * NTOK + mBase + r2] : d_bucket[e * NTOK];
    const __nv_bfloat16* aH = aHi + (size_t)aTok * Ktot + hb * 16;
    const __nv_bfloat16* aL = aLo + (size_t)aTok * Ktot + hb * 16;
    uint32_t sAoff = r2 * AROWB + hb * 32;

    int rowB = tid >> 3;            // B k-row 0..31
    int segB = tid & 7;             // B col segment base
    size_t wOff = (size_t)e * (size_t)Ktot * Ntot + (size_t)rowB * Ntot + nBase;
    const __nv_bfloat16* bH = wHi + wOff;
    const __nv_bfloat16* bL = wLo + wOff;
    uint32_t sBoff = rowB * BROWB;

    auto load_stage = [&](int st, int k0) {
        uint32_t dst = sb + st * STAGE;
        cp16(dst + OFF_AH + sAoff,      aH + k0);
        cp16(dst + OFF_AH + sAoff + 16, aH + k0 + 8);
        cp16(dst + OFF_AL + sAoff,      aL + k0);
        cp16(dst + OFF_AL + sAoff + 16, aL + k0 + 8);
        size_t kk = (size_t)k0 * Ntot;
#pragma unroll
        for (int q = 0; q < 4; q++) {
            int s = segB + q * 8;   // 0..31, 8 bf16 per seg
            cp16(dst + OFF_BH + sBoff + s * 16, bH + kk + s * 8);
            cp16(dst + OFF_BL + sBoff + s * 16, bL + kk + s * 8);
        }
    };

    // ---- compute assignment: 2 warpM x 4 warpN, warp tile 64x64 ----
    int warpM = wid >> 2;           // 0..1
    int warpN = wid & 3;            // 0..3
    int m0 = warpM * 64;
    int n0 = warpN * 64;

    float acc[32][4];
#pragma unroll
    for (int i = 0; i < 32; i++)
#pragma unroll
        for (int j = 0; j < 4; j++) acc[i][j] = 0.0f;

    int aRowL = m0 + (lane & 15);
    int aColB = (lane >> 4) * 16;
    int bKoff = (lane & 7) + ((lane >> 3) & 1) * 8;
    int bNoff = ((lane >> 4) & 1) * 8;

    auto compute_stage = [&](int st) {
        uint32_t base = sb + st * STAGE;
#pragma unroll
        for (int s = 0; s < 2; s++) {
            uint32_t ah[4][4], al[4][4];
            uint32_t aAddr = base + OFF_AH + aRowL * AROWB + aColB + s * 32;
#pragma unroll
            for (int mi = 0; mi < 4; mi++) {
                ldm4(ah[mi], aAddr + mi * 16 * AROWB);
                ldm4(al[mi], aAddr + mi * 16 * AROWB + (OFF_AL - OFF_AH));
            }
#pragma unroll
            for (int l = 0; l < 4; l++) {
                uint32_t bh[4], bl[4];
                uint32_t bAddr = base + OFF_BH + (s * 16 + bKoff) * BROWB +
                                 (n0 + l * 16 + bNoff) * 2;
                ldm4t(bh, bAddr);
                ldm4t(bl, bAddr + (OFF_BL - OFF_BH));
#pragma unroll
                for (int mi = 0; mi < 4; mi++) {
                    mma16816(acc[mi * 8 + 2 * l],     ah[mi], bh);
                    mma16816(acc[mi * 8 + 2 * l + 1], ah[mi], bh + 2);
                }
#pragma unroll
                for (int mi = 0; mi < 4; mi++) {
                    mma16816(acc[mi * 8 + 2 * l],     ah[mi], bl);
                    mma16816(acc[mi * 8 + 2 * l + 1], ah[mi], bl + 2);
                }
#pragma unroll
                for (int mi = 0; mi < 4; mi++) {
                    mma16816(acc[mi * 8 + 2 * l],     al[mi], bh);
                    mma16816(acc[mi * 8 + 2 * l + 1], al[mi], bh + 2);
                }
            }
        }
    };

    const int T = Ktot / BK;

    load_stage(0, 0);
    cp_commit();
    load_stage(1, BK);
    cp_commit();

    for (int t = 0; t < T; t++) {
        if (t == T - 1) cp_wait0(); else cp_wait1();
        __syncthreads();
        if (t + 2 < T) {
            load_stage((t + 2) % NSTAGE, (t + 2) * BK);
            cp_commit();
        }
        compute_stage(t % NSTAGE);
    }

    // ---- epilogue ----
#pragma unroll
    for (int mi = 0; mi < 4; mi++) {
#pragma unroll
        for (int half = 0; half < 2; half++) {
            int r = m0 + mi * 16 + half * 8 + (lane >> 2);
            int m = mBase + r;
            if (m >= cnt) continue;
            int token = d_bucket[e * NTOK + m];
            float sc = (MODE == 1) ? d_scale[token] : 1.0f;
#pragma unroll
            for (int nj = 0; nj < 8; nj++) {
                int col = nBase + n0 + nj * 8 + (lane & 3) * 2;
                float2 bv = *(const float2*)(bias + (size_t)e * Ntot + col);
                float v0 = acc[mi * 8 + nj][half * 2];
                float v1 = acc[mi * 8 + nj][half * 2 + 1];
                if (MODE == 1) {
                    v0 = fmaxf(v0 * sc + bv.x, 0.f);
                    v1 = fmaxf(v1 * sc + bv.y, 0.f);
                    uint32_t hw, lw;
                    split2(v0, v1, hw, lw);
                    *(uint32_t*)(oHi + (size_t)token * Ntot + col) = hw;
                    *(uint32_t*)(oLo + (size_t)token * Ntot + col) = lw;
                } else {
                    float2 o;
                    o.x = v0 + bv.x;
                    o.y = v1 + bv.y;
                    *(float2*)(out + (size_t)token * Ntot + col) = o;
                }
            }
        }
    }
}

// ---------------- finalize ---------------------------------------------------
__global__ void finalize_kernel(float* __restrict__ out, int out_size) {
    int e = threadIdx.x;
    if (e >= 8) return;
    float s = 0.0f;
    for (int b = 0; b < 512; b++) s += d_psPartial[b * 8 + e];
    const int base = NTOK * DDIM;
    if (base + e < out_size)     out[base + e]     = (float)d_expCount[e];
    if (base + 8 + e < out_size) out[base + 8 + e] = s;
    if (e == 0 && base + 16 < out_size) out[base + 16] = 0.0f;
}

// ---------------- launch -----------------------------------------------------
extern "C" void kernel_launch(void* const* d_in, const int* in_sizes, int n_in,
                              void* d_out, int out_size) {
    const float* x   = (const float*)d_in[0];
    const float* wsw = (const float*)d_in[1];
    const float* bsw = (const float*)d_in[2];
    const float* w1  = (const float*)d_in[3];
    const float* b1  = (const float*)d_in[4];
    const float* w2  = (const float*)d_in[5];
    const float* b2  = (const float*)d_in[6];
    float* out = (float*)d_out;

    cudaFuncSetAttribute(moe_gemm_kernel<1>,
                         cudaFuncAttributeMaxDynamicSharedMemorySize, SMEM_TOTAL);
    cudaFuncSetAttribute(moe_gemm_kernel<2>,
                         cudaFuncAttributeMaxDynamicSharedMemorySize, SMEM_TOTAL);

    __nv_bfloat16 *xh, *xl, *w1h, *w1l, *w2h, *w2l, *hh, *hl;
    cudaGetSymbolAddress((void**)&xh, d_x_hi);
    cudaGetSymbolAddress((void**)&xl, d_x_lo);
    cudaGetSymbolAddress((void**)&w1h, d_w1_hi);
    cudaGetSymbolAddress((void**)&w1l, d_w1_lo);
    cudaGetSymbolAddress((void**)&w2h, d_w2_hi);
    cudaGetSymbolAddress((void**)&w2l, d_w2_lo);
    cudaGetSymbolAddress((void**)&hh, d_h_hi);
    cudaGetSymbolAddress((void**)&hl, d_h_lo);

    init_kernel<<<1, 32>>>();
    route_kernel<<<512, 256>>>(x, wsw, bsw);
    splitf_kernel<<<NTOK * DDIM / 4 / 256, 256>>>(x, xh, xl);
    splitf_kernel<<<EEXP * DDIM * FDIM / 4 / 256, 256>>>(w1, w1h, w1l);
    splitf_kernel<<<EEXP * FDIM * DDIM / 4 / 256, 256>>>(w2, w2h, w2l);

    moe_gemm_kernel<1><<<dim3(FDIM / BN, NTOK / BM, EEXP), 256, SMEM_TOTAL>>>(
        xh, xl, w1h, w1l, b1, nullptr, hh, hl, FDIM, DDIM);
    moe_gemm_kernel<2><<<dim3(DDIM / BN, NTOK / BM, EEXP), 256, SMEM_TOTAL>>>(
        hh, hl, w2h, w2l, b2, out, nullptr, nullptr, DDIM, FDIM);

    finalize_kernel<<<1, 8>>>(out, out_size);
}

// round 6
// speedup vs baseline: 2.5477x; 1.2542x over previous
#include <cuda_runtime.h>
#include <cuda_fp16.h>
#include <cstdint>

#define NTOK 4096
#define DDIM 1024
#define EEXP 8
#define FDIM 4096

#define BM 128
#define BN 256
#define BK 32
#define NSTAGE 3

// smem per stage: A 128 rows x 80B (64B data + pad); B hi/lo 32 rows x 528B
#define AROWB 80
#define BROWB 528
#define OFF_A  0
#define OFF_BH 10240
#define OFF_BL 27136
#define STAGE  44032
#define SMEM_TOTAL (NSTAGE * STAGE)   // 132096

// ---------------- scratch ---------------------------------------------------
__device__ int    d_bucket[EEXP * NTOK];
__device__ int    d_expCount[EEXP];
__device__ float  d_scale[NTOK];
__device__ float  d_psPartial[512 * EEXP];
__device__ __half d_x16[(size_t)NTOK * DDIM];
__device__ __half d_w1_hi[(size_t)EEXP * DDIM * FDIM];  // [E][K][N]
__device__ __half d_w1_lo[(size_t)EEXP * DDIM * FDIM];
__device__ __half d_w2_hi[(size_t)EEXP * FDIM * DDIM];  // [E][K][N]
__device__ __half d_w2_lo[(size_t)EEXP * FDIM * DDIM];
__device__ __half d_h16[(size_t)NTOK * FDIM];

// ---------------- helpers ---------------------------------------------------
__device__ __forceinline__ uint32_t smem_u32(const void* p) {
    uint32_t a;
    asm("{ .reg .u64 t; cvta.to.shared.u64 t, %1; cvt.u32.u64 %0, t; }"
        : "=r"(a) : "l"(p));
    return a;
}
__device__ __forceinline__ void cp16(uint32_t s, const void* g) {
    asm volatile("cp.async.cg.shared.global [%0], [%1], 16;" :: "r"(s), "l"(g));
}
__device__ __forceinline__ void cp_commit() {
    asm volatile("cp.async.commit_group;" ::: "memory");
}
__device__ __forceinline__ void cp_wait1() {
    asm volatile("cp.async.wait_group 1;" ::: "memory");
}
__device__ __forceinline__ void cp_wait0() {
    asm volatile("cp.async.wait_group 0;" ::: "memory");
}
__device__ __forceinline__ void ldm4(uint32_t* r, uint32_t a) {
    asm volatile("ldmatrix.sync.aligned.m8n8.x4.shared.b16 {%0,%1,%2,%3}, [%4];"
                 : "=r"(r[0]), "=r"(r[1]), "=r"(r[2]), "=r"(r[3]) : "r"(a));
}
__device__ __forceinline__ void ldm4t(uint32_t* r, uint32_t a) {
    asm volatile("ldmatrix.sync.aligned.m8n8.x4.trans.shared.b16 {%0,%1,%2,%3}, [%4];"
                 : "=r"(r[0]), "=r"(r[1]), "=r"(r[2]), "=r"(r[3]) : "r"(a));
}
__device__ __forceinline__ void mma16816(float* c, const uint32_t* a, const uint32_t* b) {
    asm volatile("mma.sync.aligned.m16n8k16.row.col.f32.f16.f16.f32 "
                 "{%0,%1,%2,%3}, {%4,%5,%6,%7}, {%8,%9}, {%0,%1,%2,%3};"
                 : "+f"(c[0]), "+f"(c[1]), "+f"(c[2]), "+f"(c[3])
                 : "r"(a[0]), "r"(a[1]), "r"(a[2]), "r"(a[3]),
                   "r"(b[0]), "r"(b[1]));
}
__device__ __forceinline__ uint32_t pack_h2(float a, float b) {
    __half2 h = __floats2half2_rn(a, b);
    return *reinterpret_cast<uint32_t*>(&h);
}

// ---------------- init ------------------------------------------------------
__global__ void init_kernel() {
    if (threadIdx.x < EEXP) d_expCount[threadIdx.x] = 0;
}

// ---------------- routing (1 warp / token, fp64 accumulation) ---------------
__global__ void route_kernel(const float* __restrict__ x,
                             const float* __restrict__ wsw,
                             const float* __restrict__ bsw) {
    int warp = threadIdx.x >> 5;
    int lane = threadIdx.x & 31;
    int token = blockIdx.x * 8 + warp;

    const float* xr = x + (size_t)token * DDIM;
    double acc[8];
#pragma unroll
    for (int e = 0; e < 8; e++) acc[e] = 0.0;

    for (int i = lane; i < DDIM; i += 32) {
        float xv = xr[i];
        float4 wa = *(const float4*)(wsw + (size_t)i * 8);
        float4 wb = *(const float4*)(wsw + (size_t)i * 8 + 4);
        acc[0] += (double)xv * wa.x;
        acc[1] += (double)xv * wa.y;
        acc[2] += (double)xv * wa.z;
        acc[3] += (double)xv * wa.w;
        acc[4] += (double)xv * wb.x;
        acc[5] += (double)xv * wb.y;
        acc[6] += (double)xv * wb.z;
        acc[7] += (double)xv * wb.w;
    }
#pragma unroll
    for (int e = 0; e < 8; e++) {
#pragma unroll
        for (int off = 16; off > 0; off >>= 1)
            acc[e] += __shfl_down_sync(0xffffffffu, acc[e], off);
    }

    __shared__ float probs[8][8];
    if (lane == 0) {
        float l[8];
#pragma unroll
        for (int e = 0; e < 8; e++) l[e] = (float)acc[e] + bsw[e];
        int am = 0;
        float mx = l[0];
#pragma unroll
        for (int e = 1; e < 8; e++)
            if (l[e] > mx) { mx = l[e]; am = e; }
        float p[8], sum = 0.0f;
#pragma unroll
        for (int e = 0; e < 8; e++) { p[e] = expf(l[e] - mx); sum += p[e]; }
        float inv = 1.0f / sum;
#pragma unroll
        for (int e = 0; e < 8; e++) probs[warp][e] = p[e] * inv;

        d_scale[token] = inv;
        int pos = atomicAdd(&d_expCount[am], 1);
        d_bucket[am * NTOK + pos] = token;
    }
    __syncthreads();
    if (threadIdx.x < 8) {
        float s = 0.0f;
#pragma unroll
        for (int w = 0; w < 8; w++) s += probs[w][threadIdx.x];
        d_psPartial[blockIdx.x * 8 + threadIdx.x] = s;
    }
}

// ---------------- prep: weight fp32 -> fp16 hi/lo split ---------------------
__global__ void splitw_kernel(const float* __restrict__ src,
                              __half* __restrict__ hi,
                              __half* __restrict__ lo) {
    int i = blockIdx.x * blockDim.x + threadIdx.x;   // one float4 each
    float4 v = ((const float4*)src)[i];
    __half hx = __float2half_rn(v.x);
    __half hy = __float2half_rn(v.y);
    __half hz = __float2half_rn(v.z);
    __half hw = __float2half_rn(v.w);
    float lx = v.x - __half2float(hx);
    float ly = v.y - __half2float(hy);
    float lz = v.z - __half2float(hz);
    float lw = v.w - __half2float(hw);
    __half2 H0 = __halves2half2(hx, hy);
    __half2 H1 = __halves2half2(hz, hw);
    ((uint2*)hi)[i] = make_uint2(*(uint32_t*)&H0, *(uint32_t*)&H1);
    ((uint2*)lo)[i] = make_uint2(pack_h2(lx, ly), pack_h2(lz, lw));
}

// ---------------- prep: x fp32 -> fp16 --------------------------------------
__global__ void convx_kernel(const float* __restrict__ src,
                             __half* __restrict__ dst) {
    int i = blockIdx.x * blockDim.x + threadIdx.x;   // one float4 each
    float4 v = ((const float4*)src)[i];
    ((uint2*)dst)[i] = make_uint2(pack_h2(v.x, v.y), pack_h2(v.z, v.w));
}

// ---------------- grouped GEMM: fp16 A single, W split hi/lo, 2-pass --------
// MODE 1: h = relu(scale * x @ w1 + b1) -> fp16 store
// MODE 2: out = h @ w2 + b2 -> fp32 scatter
template <int MODE>
__global__ __launch_bounds__(256, 1)
void moe_gemm_kernel(const __half* __restrict__ A16,
                     const __half* __restrict__ wHi,
                     const __half* __restrict__ wLo,
                     const float* __restrict__ bias,
                     float* __restrict__ out,
                     __half* __restrict__ oF,
                     int Ntot, int Ktot) {
    int e = blockIdx.z;
    int cnt = d_expCount[e];
    int mBase = blockIdx.y * BM;
    if (mBase >= cnt) return;
    int nBase = blockIdx.x * BN;

    extern __shared__ char smem[];
    uint32_t sb = smem_u32(smem);
    int tid = threadIdx.x;
    int wid = tid >> 5;
    int lane = tid & 31;

    // ---- loader assignment ----
    int r2 = tid >> 1;              // A row 0..127
    int hb = tid & 1;               // A 32B half of the 64B row-chunk
    bool aValid = (mBase + r2) < cnt;
    int aTok = aValid ? d_bucket[e * NTOK + mBase + r2] : d_bucket[e * NTOK];
    const __half* aP = A16 + (size_t)aTok * Ktot + hb * 16;
    uint32_t sAoff = r2 * AROWB + hb * 32;

    int rowB = tid >> 3;            // B k-row 0..31
    int segB = tid & 7;
    size_t wOff = (size_t)e * (size_t)Ktot * Ntot + (size_t)rowB * Ntot + nBase;
    const __half* bH = wHi + wOff;
    const __half* bL = wLo + wOff;
    uint32_t sBoff = rowB * BROWB;

    auto load_stage = [&](int st, int k0) {
        uint32_t dst = sb + st * STAGE;
        cp16(dst + OFF_A + sAoff,      aP + k0);
        cp16(dst + OFF_A + sAoff + 16, aP + k0 + 8);
        size_t kk = (size_t)k0 * Ntot;
#pragma unroll
        for (int q = 0; q < 4; q++) {
            int s = segB + q * 8;   // 0..31 column chunks of 8 halfs
            cp16(dst + OFF_BH + sBoff + s * 16, bH + kk + s * 8);
            cp16(dst + OFF_BL + sBoff + s * 16, bL + kk + s * 8);
        }
    };

    // ---- compute assignment: 2 warpM x 4 warpN, warp tile 64x64 ----
    int warpM = wid >> 2;
    int warpN = wid & 3;
    int m0 = warpM * 64;
    int n0 = warpN * 64;

    float acc[32][4];
#pragma unroll
    for (int i = 0; i < 32; i++)
#pragma unroll
        for (int j = 0; j < 4; j++) acc[i][j] = 0.0f;

    int aRowL = m0 + (lane & 15);
    int aColB = (lane >> 4) * 16;
    int bKoff = (lane & 7) + ((lane >> 3) & 1) * 8;
    int bNoff = ((lane >> 4) & 1) * 8;

    auto compute_stage = [&](int st) {
        uint32_t base = sb + st * STAGE;
#pragma unroll
        for (int s = 0; s < 2; s++) {
            uint32_t a[4][4];
            uint32_t aAddr = base + OFF_A + aRowL * AROWB + aColB + s * 32;
#pragma unroll
            for (int mi = 0; mi < 4; mi++)
                ldm4(a[mi], aAddr + mi * 16 * AROWB);

            uint32_t bh[4][4], bl[4][4];
#pragma unroll
            for (int l = 0; l < 4; l++) {
                uint32_t bAddr = base + OFF_BH + (s * 16 + bKoff) * BROWB +
                                 (n0 + l * 16 + bNoff) * 2;
                ldm4t(bh[l], bAddr);
                ldm4t(bl[l], bAddr + (OFF_BL - OFF_BH));
            }
            // pass 1: A * B_hi  (32 independent MMAs)
#pragma unroll
            for (int mi = 0; mi < 4; mi++)
#pragma unroll
                for (int l = 0; l < 4; l++) {
                    mma16816(acc[mi * 8 + 2 * l],     a[mi], bh[l]);
                    mma16816(acc[mi * 8 + 2 * l + 1], a[mi], bh[l] + 2);
                }
            // pass 2: A * B_lo
#pragma unroll
            for (int mi = 0; mi < 4; mi++)
#pragma unroll
                for (int l = 0; l < 4; l++) {
                    mma16816(acc[mi * 8 + 2 * l],     a[mi], bl[l]);
                    mma16816(acc[mi * 8 + 2 * l + 1], a[mi], bl[l] + 2);
                }
        }
    };

    const int T = Ktot / BK;

    load_stage(0, 0);
    cp_commit();
    load_stage(1, BK);
    cp_commit();

    for (int t = 0; t < T; t++) {
        if (t == T - 1) cp_wait0(); else cp_wait1();
        __syncthreads();
        if (t + 2 < T) {
            load_stage((t + 2) % NSTAGE, (t + 2) * BK);
            cp_commit();
        }
        compute_stage(t % NSTAGE);
    }

    // ---- epilogue ----
#pragma unroll
    for (int mi = 0; mi < 4; mi++) {
#pragma unroll
        for (int half = 0; half < 2; half++) {
            int r = m0 + mi * 16 + half * 8 + (lane >> 2);
            int m = mBase + r;
            if (m >= cnt) continue;
            int token = d_bucket[e * NTOK + m];
            float sc = (MODE == 1) ? d_scale[token] : 1.0f;
#pragma unroll
            for (int nj = 0; nj < 8; nj++) {
                int col = nBase + n0 + nj * 8 + (lane & 3) * 2;
                float2 bv = *(const float2*)(bias + (size_t)e * Ntot + col);
                float v0 = acc[mi * 8 + nj][half * 2];
                float v1 = acc[mi * 8 + nj][half * 2 + 1];
                if (MODE == 1) {
                    v0 = fmaxf(v0 * sc + bv.x, 0.f);
                    v1 = fmaxf(v1 * sc + bv.y, 0.f);
                    *(uint32_t*)(oF + (size_t)token * Ntot + col) = pack_h2(v0, v1);
                } else {
                    float2 o;
                    o.x = v0 + bv.x;
                    o.y = v1 + bv.y;
                    *(float2*)(out + (size_t)token * Ntot + col) = o;
                }
            }
        }
    }
}

// ---------------- finalize ---------------------------------------------------
__global__ void finalize_kernel(float* __restrict__ out, int out_size) {
    int e = threadIdx.x;
    if (e >= 8) return;
    float s = 0.0f;
    for (int b = 0; b < 512; b++) s += d_psPartial[b * 8 + e];
    const int base = NTOK * DDIM;
    if (base + e < out_size)     out[base + e]     = (float)d_expCount[e];
    if (base + 8 + e < out_size) out[base + 8 + e] = s;
    if (e == 0 && base + 16 < out_size) out[base + 16] = 0.0f;
}

// ---------------- launch -----------------------------------------------------
extern "C" void kernel_launch(void* const* d_in, const int* in_sizes, int n_in,
                              void* d_out, int out_size) {
    const float* x   = (const float*)d_in[0];
    const float* wsw = (const float*)d_in[1];
    const float* bsw = (const float*)d_in[2];
    const float* w1  = (const float*)d_in[3];
    const float* b1  = (const float*)d_in[4];
    const float* w2  = (const float*)d_in[5];
    const float* b2  = (const float*)d_in[6];
    float* out = (float*)d_out;

    cudaFuncSetAttribute(moe_gemm_kernel<1>,
                         cudaFuncAttributeMaxDynamicSharedMemorySize, SMEM_TOTAL);
    cudaFuncSetAttribute(moe_gemm_kernel<2>,
                         cudaFuncAttributeMaxDynamicSharedMemorySize, SMEM_TOTAL);

    __half *x16, *w1h, *w1l, *w2h, *w2l, *h16;
    cudaGetSymbolAddress((void**)&x16, d_x16);
    cudaGetSymbolAddress((void**)&w1h, d_w1_hi);
    cudaGetSymbolAddress((void**)&w1l, d_w1_lo);
    cudaGetSymbolAddress((void**)&w2h, d_w2_hi);
    cudaGetSymbolAddress((void**)&w2l, d_w2_lo);
    cudaGetSymbolAddress((void**)&h16, d_h16);

    init_kernel<<<1, 32>>>();
    route_kernel<<<512, 256>>>(x, wsw, bsw);
    convx_kernel<<<NTOK * DDIM / 4 / 256, 256>>>(x, x16);
    splitw_kernel<<<EEXP * DDIM * FDIM / 4 / 256, 256>>>(w1, w1h, w1l);
    splitw_kernel<<<EEXP * FDIM * DDIM / 4 / 256, 256>>>(w2, w2h, w2l);

    moe_gemm_kernel<1><<<dim3(FDIM / BN, NTOK / BM, EEXP), 256, SMEM_TOTAL>>>(
        x16, w1h, w1l, b1, nullptr, h16, FDIM, DDIM);
    moe_gemm_kernel<2><<<dim3(DDIM / BN, NTOK / BM, EEXP), 256, SMEM_TOTAL>>>(
        h16, w2h, w2l, b2, out, nullptr, DDIM, FDIM);

    finalize_kernel<<<1, 8>>>(out, out_size);
}